// round 1
// baseline (speedup 1.0000x reference)
#include <cuda_runtime.h>

#define BB   16
#define CINC 256
#define COUT 128
#define HH   64
#define WW   64
#define OH   128
#define OW   128

// Per-sample, phase/tap-reordered weights: [b][phase(4)][ic][tap(4)][oc]
// phase = py*2+px,  tap = tky*2+tkx
// py=0 taps: ky=1 (dy=0), ky=3 (dy=-1);  py=1 taps: ky=0 (dy=+1), ky=2 (dy=0)
// (same for kx / px).  Mapping from (ky): py = 1-(ky&1), tky = ky>>1.
__device__ float g_w[BB * 4 * CINC * 4 * COUT];   // 32 MB scratch (static, allowed)

// ---------------------------------------------------------------------------
// Kernel 1: weight synthesis.  One block per ic (256 blocks, 256 threads).
// Each thread owns 8 of the 2048 (oc,ky,kx) elements of this ic, loops over b.
// ---------------------------------------------------------------------------
__global__ __launch_bounds__(256) void synth_kernel(
    const float* __restrict__ feature,            // (16,4)
    const float* __restrict__ w0,                 // (256,128,4,4)
    const float* __restrict__ tb, const float* __restrict__ tq,
    const float* __restrict__ tn, const float* __restrict__ tx,
    const float* __restrict__ mb, const float* __restrict__ mq,
    const float* __restrict__ mn, const float* __restrict__ mx)
{
    __shared__ float sf[64];
    __shared__ float buf[2048];                   // [phase][tap][oc] for one (b, ic)

    const int ic = blockIdx.x;
    const int t  = threadIdx.x;
    if (t < 64) sf[t] = feature[t];
    __syncthreads();

    float base[8], ub[8], uq[8], un[8], ux[8];
    int   sidx[8];
    const int off = ic * 2048;

#pragma unroll
    for (int j = 0; j < 8; j++) {
        const int idx = t + 256 * j;              // = oc*16 + ky*4 + kx
        const int oc  = idx >> 4;
        const int kk  = idx & 15;
        const int ky  = kk >> 2, kx = kk & 3;
        const float mB = mb[ic * COUT + oc], mQ = mq[ic * COUT + oc];
        const float mN = mn[ic * COUT + oc], mX = mx[ic * COUT + oc];
        base[j] = w0[off + idx];
        ub[j] = tb[off + idx] * mB;
        uq[j] = tq[off + idx] * mQ;
        un[j] = tn[off + idx] * mN;
        ux[j] = tx[off + idx] * mX;
        const int py = 1 - (ky & 1), px = 1 - (kx & 1);
        const int tap = (ky >> 1) * 2 + (kx >> 1);
        sidx[j] = (py * 2 + px) * 512 + tap * 128 + oc;
    }

    for (int b = 0; b < BB; b++) {
        const float f0 = sf[b * 4 + 0], f1 = sf[b * 4 + 1];
        const float f2 = sf[b * 4 + 2], f3 = sf[b * 4 + 3];
#pragma unroll
        for (int j = 0; j < 8; j++)
            buf[sidx[j]] = base[j] + f0 * ub[j] + f1 * uq[j] + f2 * un[j] + f3 * ux[j];
        __syncthreads();
#pragma unroll
        for (int p = 0; p < 4; p++) {
#pragma unroll
            for (int j = 0; j < 2; j++) {
                const int e = t + j * 256;        // 0..511
                g_w[((b * 4 + p) * CINC + ic) * 512 + e] = buf[p * 512 + e];
            }
        }
        __syncthreads();
    }
}

// ---------------------------------------------------------------------------
// Kernel 2: phase-separated implicit-GEMM transposed conv.
// Grid: (ytile=16, phase=4, b=16).  Block tile: 128 oc x (4 rows x 64 cols).
// Thread tile: 8 oc x 16 px  (128 fp32 accumulators).
// ---------------------------------------------------------------------------
__global__ __launch_bounds__(256) void deconv_kernel(
    const float* __restrict__ x,                  // (16,256,64,64)
    const float* __restrict__ bias,               // (128,)
    const float* __restrict__ prelu_a,            // (1,)
    float* __restrict__ out)                      // (16,128,128,128)
{
    __shared__ float sw[8 * 4 * 128];             // [ic_local*4 + tap][oc]   16 KB
    __shared__ float sx[8 * 5 * 68];              // [ic_local][row(5)][col(65 pad 68)]

    const int ytile = blockIdx.x;                 // 0..15
    const int phase = blockIdx.y;                 // 0..3
    const int b     = blockIdx.z;                 // 0..15
    const int py = phase >> 1, px = phase & 1;

    const int t  = threadIdx.x;
    const int to = t >> 4;                        // oc group: oc_base = to*8
    const int tp = t & 15;
    const int r  = tp >> 2;                       // row within tile (0..3)
    const int c0 = (tp & 3) * 16;                 // col segment start

    const int y0    = ytile * 4;
    const int dymin = (py == 0) ? -1 : 0;
    const int dxmin = (px == 0) ? -1 : 0;

    float acc[8][16];
#pragma unroll
    for (int o = 0; o < 8; o++)
#pragma unroll
        for (int p = 0; p < 16; p++) acc[o][p] = 0.f;

    const float* gw = g_w + (size_t)((b * 4 + phase) * CINC) * 512;
    const float* xb = x + (size_t)b * CINC * HH * WW;

    for (int ic0 = 0; ic0 < CINC; ic0 += 8) {
        // --- stage weights: 4096 contiguous floats ---
        const float4* gw4 = reinterpret_cast<const float4*>(gw + ic0 * 512);
        float4* sw4 = reinterpret_cast<float4*>(sw);
#pragma unroll
        for (int j = 0; j < 4; j++) sw4[t + 256 * j] = gw4[t + 256 * j];

        // --- stage x tile with zero-filled halo: 8 ic x 5 rows x 65 cols ---
        for (int idx = t; idx < 8 * 5 * 65; idx += 256) {
            const int i  = idx % 65;
            const int jj = (idx / 65) % 5;
            const int ii = idx / 325;
            const int gy = y0 + dymin + jj;
            const int gx = dxmin + i;
            float v = 0.f;
            if ((unsigned)gy < 64u && (unsigned)gx < 64u)
                v = xb[(ic0 + ii) * (HH * WW) + gy * WW + gx];
            sx[(ii * 5 + jj) * 68 + i] = v;
        }
        __syncthreads();

#pragma unroll 2
        for (int il = 0; il < 8; il++) {
#pragma unroll
            for (int tky = 0; tky < 2; tky++) {
                float xrow[17];
                const float* sxr = sx + (il * 5 + (r + 1 - tky)) * 68 + c0;
#pragma unroll
                for (int i = 0; i < 17; i++) xrow[i] = sxr[i];
#pragma unroll
                for (int tkx = 0; tkx < 2; tkx++) {
                    const float* swr = sw + (il * 4 + tky * 2 + tkx) * 128 + to * 8;
                    float w8[8];
#pragma unroll
                    for (int o = 0; o < 8; o++) w8[o] = swr[o];
#pragma unroll
                    for (int o = 0; o < 8; o++)
#pragma unroll
                        for (int p = 0; p < 16; p++)
                            acc[o][p] += w8[o] * xrow[p + 1 - tkx];
                }
            }
        }
        __syncthreads();
    }

    // --- epilogue: bias + PReLU, direct store ---
    const float pa  = prelu_a[0];
    const int   ocb = to * 8;
    const int   oy  = 2 * (y0 + r) + py;
#pragma unroll
    for (int o = 0; o < 8; o++) {
        const float bz = bias[ocb + o];
        float* orow = out + (((size_t)(b * COUT + ocb + o)) * OH + oy) * OW + px;
#pragma unroll
        for (int p = 0; p < 16; p++) {
            float v = acc[o][p] + bz;
            v = (v >= 0.f) ? v : pa * v;
            orow[2 * (c0 + p)] = v;
        }
    }
}

// ---------------------------------------------------------------------------
extern "C" void kernel_launch(void* const* d_in, const int* in_sizes, int n_in,
                              void* d_out, int out_size)
{
    const float* x       = (const float*)d_in[0];
    const float* feature = (const float*)d_in[1];
    const float* weight  = (const float*)d_in[2];
    const float* tb      = (const float*)d_in[3];
    const float* tq      = (const float*)d_in[4];
    const float* tn      = (const float*)d_in[5];
    const float* tx      = (const float*)d_in[6];
    const float* mb      = (const float*)d_in[7];
    const float* mq      = (const float*)d_in[8];
    const float* mn      = (const float*)d_in[9];
    const float* mx      = (const float*)d_in[10];
    const float* bias    = (const float*)d_in[11];
    const float* prelu_a = (const float*)d_in[12];
    float* out = (float*)d_out;

    synth_kernel<<<CINC, 256>>>(feature, weight, tb, tq, tn, tx, mb, mq, mn, mx);

    dim3 grid(16, 4, 16);
    deconv_kernel<<<grid, 256>>>(x, bias, prelu_a, out);
}